// round 3
// baseline (speedup 1.0000x reference)
#include <cuda_runtime.h>
#include <math.h>

// ---------------- problem constants ----------------
#define BB 4
#define LL 5
#define HW 1024          // HS*WS = 32*32
#define CC 256
#define MM 8
#define DD 32
#define TT 2
#define II 256           // M*D
#define NTOK (BB*LL*HW)  // 20480
#define TOKELEMS (NTOK*CC) // 5,242,880

// ---------------- scratch (static device globals; allocation-free) --------
__device__ __align__(16) float g_xn[TOKELEMS];
__device__ __align__(16) float g_q [TOKELEMS];
__device__ __align__(16) float g_k [TOKELEMS];
__device__ __align__(16) float g_v [TOKELEMS];
__device__ __align__(16) float g_ao[TOKELEMS];

// =====================================================================
// Kernel 1: LayerNorm over C=256 per token. One warp per token.
// =====================================================================
__global__ __launch_bounds__(256) void k_ln(const float* __restrict__ x,
                                            const float* __restrict__ lw,
                                            const float* __restrict__ lb)
{
    int warp = threadIdx.x >> 5;
    int lane = threadIdx.x & 31;
    int tok  = (blockIdx.x << 3) + warp;           // grid = 2560 -> 20480 tokens

    const float4* xr = reinterpret_cast<const float4*>(x + (size_t)tok * CC);
    float4 v0 = xr[lane];
    float4 v1 = xr[lane + 32];

    float s  = v0.x + v0.y + v0.z + v0.w + v1.x + v1.y + v1.z + v1.w;
    float sq = v0.x*v0.x + v0.y*v0.y + v0.z*v0.z + v0.w*v0.w
             + v1.x*v1.x + v1.y*v1.y + v1.z*v1.z + v1.w*v1.w;
    #pragma unroll
    for (int off = 16; off >= 1; off >>= 1) {
        s  += __shfl_xor_sync(0xffffffffu, s,  off);
        sq += __shfl_xor_sync(0xffffffffu, sq, off);
    }
    float mean = s * (1.0f / 256.0f);
    float var  = sq * (1.0f / 256.0f) - mean * mean;
    float rstd = rsqrtf(var + 1e-5f);

    const float4* w4 = reinterpret_cast<const float4*>(lw);
    const float4* b4 = reinterpret_cast<const float4*>(lb);
    float4 w0 = w4[lane], w1 = w4[lane + 32];
    float4 b0 = b4[lane], b1 = b4[lane + 32];

    float4 o0, o1;
    o0.x = (v0.x - mean) * rstd * w0.x + b0.x;
    o0.y = (v0.y - mean) * rstd * w0.y + b0.y;
    o0.z = (v0.z - mean) * rstd * w0.z + b0.z;
    o0.w = (v0.w - mean) * rstd * w0.w + b0.w;
    o1.x = (v1.x - mean) * rstd * w1.x + b1.x;
    o1.y = (v1.y - mean) * rstd * w1.y + b1.y;
    o1.z = (v1.z - mean) * rstd * w1.z + b1.z;
    o1.w = (v1.w - mean) * rstd * w1.w + b1.w;

    float4* orow = reinterpret_cast<float4*>(g_xn + (size_t)tok * CC);
    orow[lane]      = o0;
    orow[lane + 32] = o1;
}

// =====================================================================
// Shared GEMM core: C_tile[128x128] = A[1024x256] * W[256x256..] + bias
// A row-major (lda=256), W row-major (ldw=256), Out row-major (ldo=256).
// 256 threads, 8x8 per-thread microtile, BK=16.
// =====================================================================
__device__ __forceinline__ void gemm_block(const float* __restrict__ A,
                                           const float* __restrict__ W,
                                           const float* __restrict__ bias,
                                           float* __restrict__ Out,
                                           int m0, int ncol0)
{
    __shared__ __align__(16) float As[16][132];  // transposed A tile, padded
    __shared__ __align__(16) float Bs[16][128];

    int tid = threadIdx.x;
    int tm = (tid >> 4) << 3;    // 0..120
    int tn = (tid & 15) << 3;    // 0..120

    float acc[8][8];
    #pragma unroll
    for (int i = 0; i < 8; ++i)
        #pragma unroll
        for (int j = 0; j < 8; ++j) acc[i][j] = 0.0f;

    for (int kt = 0; kt < 256; kt += 16) {
        // load A tile (transpose into As[k][m])
        #pragma unroll
        for (int it = 0; it < 2; ++it) {
            int pos = tid + it * 256;          // 0..511 float4 slots
            int row = pos >> 2;                // 0..127
            int kq  = (pos & 3) << 2;          // 0,4,8,12
            float4 a = *reinterpret_cast<const float4*>(
                A + (size_t)(m0 + row) * 256 + kt + kq);
            As[kq + 0][row] = a.x;
            As[kq + 1][row] = a.y;
            As[kq + 2][row] = a.z;
            As[kq + 3][row] = a.w;
        }
        // load B tile
        #pragma unroll
        for (int it = 0; it < 2; ++it) {
            int pos = tid + it * 256;
            int rk = pos >> 5;                 // 0..15
            int nc = (pos & 31) << 2;          // 0..124
            *reinterpret_cast<float4*>(&Bs[rk][nc]) =
                *reinterpret_cast<const float4*>(W + (size_t)(kt + rk) * 256 + ncol0 + nc);
        }
        __syncthreads();

        #pragma unroll
        for (int kk = 0; kk < 16; ++kk) {
            float ar[8], br[8];
            float4 a0 = *reinterpret_cast<const float4*>(&As[kk][tm]);
            float4 a1 = *reinterpret_cast<const float4*>(&As[kk][tm + 4]);
            float4 b0 = *reinterpret_cast<const float4*>(&Bs[kk][tn]);
            float4 b1 = *reinterpret_cast<const float4*>(&Bs[kk][tn + 4]);
            ar[0]=a0.x; ar[1]=a0.y; ar[2]=a0.z; ar[3]=a0.w;
            ar[4]=a1.x; ar[5]=a1.y; ar[6]=a1.z; ar[7]=a1.w;
            br[0]=b0.x; br[1]=b0.y; br[2]=b0.z; br[3]=b0.w;
            br[4]=b1.x; br[5]=b1.y; br[6]=b1.z; br[7]=b1.w;
            #pragma unroll
            for (int i = 0; i < 8; ++i)
                #pragma unroll
                for (int j = 0; j < 8; ++j)
                    acc[i][j] = fmaf(ar[i], br[j], acc[i][j]);
        }
        __syncthreads();
    }

    // epilogue: + bias, vectorized store
    #pragma unroll
    for (int i = 0; i < 8; ++i) {
        float* orow = Out + (size_t)(m0 + tm + i) * 256 + ncol0 + tn;
        const float* brow = bias + ncol0 + tn;
        float4 r0, r1;
        r0.x = acc[i][0] + brow[0];
        r0.y = acc[i][1] + brow[1];
        r0.z = acc[i][2] + brow[2];
        r0.w = acc[i][3] + brow[3];
        r1.x = acc[i][4] + brow[4];
        r1.y = acc[i][5] + brow[5];
        r1.z = acc[i][6] + brow[6];
        r1.w = acc[i][7] + brow[7];
        *reinterpret_cast<float4*>(orow)     = r0;
        *reinterpret_cast<float4*>(orow + 4) = r1;
    }
}

// =====================================================================
// Kernel 2: fused Q/K/V projection. grid = (8 mtiles, 6 ntiles, 20 bl)
// ntile: 0,1 -> Q cols 0..255 ; 2,3 -> K ; 4,5 -> V
// =====================================================================
__global__ __launch_bounds__(256) void k_gemm_qkv(const float* __restrict__ pe,
                                                  const float* __restrict__ Wq,
                                                  const float* __restrict__ bq,
                                                  const float* __restrict__ Wk,
                                                  const float* __restrict__ bk,
                                                  const float* __restrict__ Wv,
                                                  const float* __restrict__ bv)
{
    int bl = blockIdx.z;
    int t  = (int)pe[(size_t)bl * 3072 + 2];     // prior_encoding[b,l,0,0,2]
    int sel   = blockIdx.y >> 1;
    int ncol0 = (blockIdx.y & 1) << 7;

    const float* W;
    const float* bias;
    float* out;
    if (sel == 0)      { W = Wq; bias = bq; out = g_q; }
    else if (sel == 1) { W = Wk; bias = bk; out = g_k; }
    else               { W = Wv; bias = bv; out = g_v; }

    gemm_block(g_xn + (size_t)bl * HW * CC,
               W + (size_t)t * CC * II,
               bias + (size_t)t * II,
               out + (size_t)bl * HW * II,
               blockIdx.x << 7, ncol0);
}

// =====================================================================
// Kernel 3: fused HGT attention.
// Block = 256 threads (8 warps), each warp owns one (b, m, hw).
// Exploits: transform k/v by only T=2 query-type matrices instead of L=5.
// grid = B*M*(HW/8) = 4096
// =====================================================================
__global__ __launch_bounds__(256) void k_attn(const int*   __restrict__ mask,
                                              const float* __restrict__ pe,
                                              const float* __restrict__ rel_att,
                                              const float* __restrict__ rel_msg)
{
    __shared__ float Wa_s[4][33 * 32];   // att weights, layout [r][q*33 + p]
    __shared__ float Wm_s[4][33 * 32];   // msg weights, layout [r][p*33 + c]
    __shared__ float ks_s[8][LL][32];
    __shared__ float vs_s[8][LL][32];
    __shared__ int   ts_s[LL];

    int tid  = threadIdx.x;
    int lane = tid & 31;
    int w    = tid >> 5;
    int bidx = blockIdx.x;
    int hw   = ((bidx & 127) << 3) + w;
    int m    = (bidx >> 7) & 7;
    int b    = bidx >> 10;

    if (tid < LL) ts_s[tid] = (int)pe[(size_t)(b * LL + tid) * 3072 + 2];

    // stage relation matrices for this head (4 e-values, both att & msg)
    for (int idx = tid; idx < 4096; idx += 256) {
        int r   = idx >> 10;
        int rem = idx & 1023;
        int p   = rem >> 5;
        int qq  = rem & 31;
        size_t goff = (size_t)(r * MM + m) * 1024 + rem;
        Wa_s[r][qq * 33 + p] = rel_att[goff];   // transposed: [q][p]
        Wm_s[r][p * 33 + qq] = rel_msg[goff];   // direct:     [p][c]
    }

    // stage q (regs) and k/v (smem) for this (b,m,hw) across all L positions
    float qreg[LL];
    int base_off = (m << 5) + lane;
    #pragma unroll
    for (int j = 0; j < LL; ++j) {
        size_t tok = (size_t)((b * LL + j) << 10) + hw;
        qreg[j]        = g_q[tok * II + base_off];
        ks_s[w][j][lane] = g_k[tok * II + base_off];
        vs_s[w][j][lane] = g_v[tok * II + base_off];
    }
    __syncthreads();

    // relation transforms: k'_{j,ti}[p] = sum_q Watt[ti*2+tj][p][q] k_j[q]
    //                      v'_{j,ti}[c] = sum_p Wmsg[ti*2+tj][p][c] v_j[p]
    float kp[LL][2], vp[LL][2];
    #pragma unroll
    for (int j = 0; j < LL; ++j) {
        int tj = ts_s[j];
        const float* WA0 = Wa_s[tj];
        const float* WA1 = Wa_s[2 + tj];
        const float* WM0 = Wm_s[tj];
        const float* WM1 = Wm_s[2 + tj];
        float a0 = 0.f, a1 = 0.f, s0 = 0.f, s1 = 0.f;
        #pragma unroll
        for (int qq = 0; qq < 32; ++qq) {
            float kv = ks_s[w][j][qq];
            float vv = vs_s[w][j][qq];
            int off = qq * 33 + lane;
            a0 = fmaf(WA0[off], kv, a0);
            a1 = fmaf(WA1[off], kv, a1);
            s0 = fmaf(WM0[off], vv, s0);
            s1 = fmaf(WM1[off], vv, s1);
        }
        kp[j][0] = a0; kp[j][1] = a1;
        vp[j][0] = s0; vp[j][1] = s1;
    }

    // att[i][j] = scale * q_i . k'_{j, t_i}   (warp reduce over D)
    float att[LL][LL];
    #pragma unroll
    for (int i = 0; i < LL; ++i) {
        int ti = ts_s[i];
        #pragma unroll
        for (int j = 0; j < LL; ++j) {
            float kpv  = ti ? kp[j][1] : kp[j][0];
            float part = qreg[i] * kpv;
            part += __shfl_xor_sync(0xffffffffu, part, 16);
            part += __shfl_xor_sync(0xffffffffu, part, 8);
            part += __shfl_xor_sync(0xffffffffu, part, 4);
            part += __shfl_xor_sync(0xffffffffu, part, 2);
            part += __shfl_xor_sync(0xffffffffu, part, 1);
            att[i][j] = part * 0.17677669529663687f;   // D^-0.5
        }
    }

    // mask + softmax + weighted message accumulation + store
    const int* mrow = mask + ((size_t)(b << 10) + hw) * 25;
    #pragma unroll
    for (int i = 0; i < LL; ++i) {
        float mx = -1e30f;
        #pragma unroll
        for (int j = 0; j < LL; ++j) {
            if (mrow[i * 5 + j] == 0) att[i][j] = -1e9f;
            mx = fmaxf(mx, att[i][j]);
        }
        float s = 0.f;
        #pragma unroll
        for (int j = 0; j < LL; ++j) {
            float e = __expf(att[i][j] - mx);
            att[i][j] = e;
            s += e;
        }
        float inv = 1.0f / s;
        int ti = ts_s[i];
        float o = 0.f;
        #pragma unroll
        for (int j = 0; j < LL; ++j) {
            float vpv = ti ? vp[j][1] : vp[j][0];
            o = fmaf(att[i][j], vpv, o);
        }
        size_t tok = (size_t)((b * LL + i) << 10) + hw;
        g_ao[tok * II + base_off] = o * inv;
    }
}

// =====================================================================
// Kernel 4: output projection + bias -> final output (token-major already
// matches [B,L,H,W,C]). grid = (8 mtiles, 2 ntiles, 20 bl)
// =====================================================================
__global__ __launch_bounds__(256) void k_gemm_ao(const float* __restrict__ pe,
                                                 const float* __restrict__ Wa,
                                                 const float* __restrict__ ba,
                                                 float* __restrict__ out)
{
    int bl = blockIdx.z;
    int t  = (int)pe[(size_t)bl * 3072 + 2];
    gemm_block(g_ao + (size_t)bl * HW * II,
               Wa + (size_t)t * II * CC,
               ba + (size_t)t * CC,
               out + (size_t)bl * HW * CC,
               blockIdx.x << 7, (blockIdx.y & 1) << 7);
}

// =====================================================================
extern "C" void kernel_launch(void* const* d_in, const int* in_sizes, int n_in,
                              void* d_out, int out_size)
{
    const float* x    = (const float*)d_in[0];
    const int*   mask = (const int*)  d_in[1];
    const float* pe   = (const float*)d_in[2];
    const float* lnw  = (const float*)d_in[3];
    const float* lnb  = (const float*)d_in[4];
    const float* Wq   = (const float*)d_in[5];
    const float* bq   = (const float*)d_in[6];
    const float* Wk   = (const float*)d_in[7];
    const float* bk   = (const float*)d_in[8];
    const float* Wv   = (const float*)d_in[9];
    const float* bv   = (const float*)d_in[10];
    const float* Wa   = (const float*)d_in[11];
    const float* ba   = (const float*)d_in[12];
    const float* ra   = (const float*)d_in[13];
    const float* rm   = (const float*)d_in[14];
    float* out = (float*)d_out;

    k_ln<<<2560, 256>>>(x, lnw, lnb);

    dim3 g1(8, 6, 20);
    k_gemm_qkv<<<g1, 256>>>(pe, Wq, bq, Wk, bk, Wv, bv);

    k_attn<<<4096, 256>>>(mask, pe, ra, rm);

    dim3 g2(8, 2, 20);
    k_gemm_ao<<<g2, 256>>>(pe, Wa, ba, out);
}

// round 4
// speedup vs baseline: 1.6455x; 1.6455x over previous
#include <cuda_runtime.h>
#include <math.h>

// ---------------- problem constants ----------------
#define BB 4
#define LL 5
#define HW 1024          // HS*WS = 32*32
#define CC 256
#define MM 8
#define DD 32
#define TT 2
#define II 256           // M*D
#define NTOK (BB*LL*HW)  // 20480
#define TOKELEMS (NTOK*CC) // 5,242,880

// ---------------- scratch (static device globals; allocation-free) --------
__device__ __align__(16) float g_xn[TOKELEMS];
__device__ __align__(16) float g_q [TOKELEMS];
__device__ __align__(16) float g_k [TOKELEMS];
__device__ __align__(16) float g_v [TOKELEMS];
__device__ __align__(16) float g_ao[TOKELEMS];

// =====================================================================
// Kernel 1: LayerNorm over C=256 per token. One warp per token.
// =====================================================================
__global__ __launch_bounds__(256) void k_ln(const float* __restrict__ x,
                                            const float* __restrict__ lw,
                                            const float* __restrict__ lb)
{
    int warp = threadIdx.x >> 5;
    int lane = threadIdx.x & 31;
    int tok  = (blockIdx.x << 3) + warp;           // grid = 2560 -> 20480 tokens

    const float4* xr = reinterpret_cast<const float4*>(x + (size_t)tok * CC);
    float4 v0 = xr[lane];
    float4 v1 = xr[lane + 32];

    float s  = v0.x + v0.y + v0.z + v0.w + v1.x + v1.y + v1.z + v1.w;
    float sq = v0.x*v0.x + v0.y*v0.y + v0.z*v0.z + v0.w*v0.w
             + v1.x*v1.x + v1.y*v1.y + v1.z*v1.z + v1.w*v1.w;
    #pragma unroll
    for (int off = 16; off >= 1; off >>= 1) {
        s  += __shfl_xor_sync(0xffffffffu, s,  off);
        sq += __shfl_xor_sync(0xffffffffu, sq, off);
    }
    float mean = s * (1.0f / 256.0f);
    float var  = sq * (1.0f / 256.0f) - mean * mean;
    float rstd = rsqrtf(var + 1e-5f);

    const float4* w4 = reinterpret_cast<const float4*>(lw);
    const float4* b4 = reinterpret_cast<const float4*>(lb);
    float4 w0 = w4[lane], w1 = w4[lane + 32];
    float4 b0 = b4[lane], b1 = b4[lane + 32];

    float4 o0, o1;
    o0.x = (v0.x - mean) * rstd * w0.x + b0.x;
    o0.y = (v0.y - mean) * rstd * w0.y + b0.y;
    o0.z = (v0.z - mean) * rstd * w0.z + b0.z;
    o0.w = (v0.w - mean) * rstd * w0.w + b0.w;
    o1.x = (v1.x - mean) * rstd * w1.x + b1.x;
    o1.y = (v1.y - mean) * rstd * w1.y + b1.y;
    o1.z = (v1.z - mean) * rstd * w1.z + b1.z;
    o1.w = (v1.w - mean) * rstd * w1.w + b1.w;

    float4* orow = reinterpret_cast<float4*>(g_xn + (size_t)tok * CC);
    orow[lane]      = o0;
    orow[lane + 32] = o1;
}

// =====================================================================
// tf32 helpers
// =====================================================================
__device__ __forceinline__ unsigned f2tf(float f) {
    unsigned u;
    asm("cvt.rna.tf32.f32 %0, %1;" : "=r"(u) : "f"(f));
    return u;
}

__device__ __forceinline__ void mma_tf32(float c[4],
                                         unsigned a0, unsigned a1, unsigned a2, unsigned a3,
                                         unsigned b0, unsigned b1)
{
    asm volatile(
        "mma.sync.aligned.m16n8k8.row.col.f32.tf32.tf32.f32 "
        "{%0,%1,%2,%3}, {%4,%5,%6,%7}, {%8,%9}, {%0,%1,%2,%3};"
        : "+f"(c[0]), "+f"(c[1]), "+f"(c[2]), "+f"(c[3])
        : "r"(a0), "r"(a1), "r"(a2), "r"(a3), "r"(b0), "r"(b1));
}

// XOR swizzle for the transposed A tile: makes both the transposing STS and
// the fragment LDS conflict-free.
#define ASW(k, m) ((m) ^ (((((k) >> 2)) & 7) << 2))

// =====================================================================
// tf32 tensor-core GEMM tile: Out[128x128] = A[128x256] * W[256x128] + bias
// A row-major (lda=256), W row-major (ldw=256), Out row-major (ldo=256).
// 256 threads = 8 warps (2x4), warp tile 64x32, m16n8k8 tf32 MMA, BK=32,
// register prefetch of next K-chunk.
// =====================================================================
__device__ __forceinline__ void gemm_tf32(const float* __restrict__ A,
                                          const float* __restrict__ W,
                                          const float* __restrict__ bias,
                                          float* __restrict__ Out,
                                          int m0, int ncol0)
{
    __shared__ __align__(16) unsigned As[32][136];  // transposed [k][m], swizzled
    __shared__ __align__(16) unsigned Bs[32][136];  // [k][n]

    const int tid  = threadIdx.x;
    const int lane = tid & 31;
    const int warp = tid >> 5;
    const int wm = (warp >> 2) << 6;   // 0 or 64
    const int wn = (warp & 3)  << 5;   // 0,32,64,96

    float acc[4][4][4];
    #pragma unroll
    for (int mt = 0; mt < 4; ++mt)
        #pragma unroll
        for (int nt = 0; nt < 4; ++nt)
            #pragma unroll
            for (int r = 0; r < 4; ++r) acc[mt][nt][r] = 0.0f;

    // loader index precompute
    //  A: pos = tid + it*256 (it<4): row = pos>>3 (0..127), kq = (pos&7)*4
    //  B: krow = pos>>5 (0..31), nc = (pos&31)*4
    float4 pa[4], pb[4];
    #pragma unroll
    for (int it = 0; it < 4; ++it) {
        int pos  = tid + (it << 8);
        int arow = pos >> 3, akq = (pos & 7) << 2;
        int brow = pos >> 5, bnc = (pos & 31) << 2;
        pa[it] = *reinterpret_cast<const float4*>(A + (size_t)(m0 + arow) * 256 + akq);
        pb[it] = *reinterpret_cast<const float4*>(W + (size_t)brow * 256 + ncol0 + bnc);
    }

    for (int ch = 0; ch < 8; ++ch) {
        // ---- stage current chunk into smem (cvt to tf32) ----
        #pragma unroll
        for (int it = 0; it < 4; ++it) {
            int pos  = tid + (it << 8);
            int arow = pos >> 3, akq = (pos & 7) << 2;
            As[akq + 0][ASW(akq + 0, arow)] = f2tf(pa[it].x);
            As[akq + 1][ASW(akq + 1, arow)] = f2tf(pa[it].y);
            As[akq + 2][ASW(akq + 2, arow)] = f2tf(pa[it].z);
            As[akq + 3][ASW(akq + 3, arow)] = f2tf(pa[it].w);
            int brow = pos >> 5, bnc = (pos & 31) << 2;
            uint4 bb;
            bb.x = f2tf(pb[it].x); bb.y = f2tf(pb[it].y);
            bb.z = f2tf(pb[it].z); bb.w = f2tf(pb[it].w);
            *reinterpret_cast<uint4*>(&Bs[brow][bnc]) = bb;
        }
        __syncthreads();

        // ---- prefetch next chunk ----
        if (ch < 7) {
            int kc = (ch + 1) << 5;
            #pragma unroll
            for (int it = 0; it < 4; ++it) {
                int pos  = tid + (it << 8);
                int arow = pos >> 3, akq = (pos & 7) << 2;
                int brow = pos >> 5, bnc = (pos & 31) << 2;
                pa[it] = *reinterpret_cast<const float4*>(A + (size_t)(m0 + arow) * 256 + kc + akq);
                pb[it] = *reinterpret_cast<const float4*>(W + (size_t)(kc + brow) * 256 + ncol0 + bnc);
            }
        }

        // ---- 4 MMA k-steps of k=8 ----
        #pragma unroll
        for (int ks = 0; ks < 4; ++ks) {
            int k0 = ks << 3;
            int kr = k0 + (lane & 3);
            unsigned afr[4][4], bfr[4][2];
            #pragma unroll
            for (int mt = 0; mt < 4; ++mt) {
                int mcol = wm + (mt << 4) + (lane >> 2);
                afr[mt][0] = As[kr    ][ASW(kr,     mcol)];
                afr[mt][1] = As[kr    ][ASW(kr,     mcol + 8)];
                afr[mt][2] = As[kr + 4][ASW(kr + 4, mcol)];
                afr[mt][3] = As[kr + 4][ASW(kr + 4, mcol + 8)];
            }
            #pragma unroll
            for (int nt = 0; nt < 4; ++nt) {
                int nc = wn + (nt << 3) + (lane >> 2);
                bfr[nt][0] = Bs[kr    ][nc];
                bfr[nt][1] = Bs[kr + 4][nc];
            }
            #pragma unroll
            for (int mt = 0; mt < 4; ++mt)
                #pragma unroll
                for (int nt = 0; nt < 4; ++nt)
                    mma_tf32(acc[mt][nt],
                             afr[mt][0], afr[mt][1], afr[mt][2], afr[mt][3],
                             bfr[nt][0], bfr[nt][1]);
        }
        __syncthreads();
    }

    // ---- epilogue: + bias, float2 stores ----
    #pragma unroll
    for (int mt = 0; mt < 4; ++mt) {
        int mrow = m0 + wm + (mt << 4) + (lane >> 2);
        #pragma unroll
        for (int nt = 0; nt < 4; ++nt) {
            int nc = ncol0 + wn + (nt << 3) + ((lane & 3) << 1);
            float b0 = bias[nc], b1 = bias[nc + 1];
            float2 r0, r1;
            r0.x = acc[mt][nt][0] + b0; r0.y = acc[mt][nt][1] + b1;
            r1.x = acc[mt][nt][2] + b0; r1.y = acc[mt][nt][3] + b1;
            *reinterpret_cast<float2*>(Out + (size_t)mrow * 256 + nc)       = r0;
            *reinterpret_cast<float2*>(Out + (size_t)(mrow + 8) * 256 + nc) = r1;
        }
    }
}

// =====================================================================
// Kernel 2: fused Q/K/V projection. grid = (8 mtiles, 6 ntiles, 20 bl)
// =====================================================================
__global__ __launch_bounds__(256, 1) void k_gemm_qkv(const float* __restrict__ pe,
                                                     const float* __restrict__ Wq,
                                                     const float* __restrict__ bq,
                                                     const float* __restrict__ Wk,
                                                     const float* __restrict__ bk,
                                                     const float* __restrict__ Wv,
                                                     const float* __restrict__ bv)
{
    int bl = blockIdx.z;
    int t  = (int)pe[(size_t)bl * 3072 + 2];     // prior_encoding[b,l,0,0,2]
    int sel   = blockIdx.y >> 1;
    int ncol0 = (blockIdx.y & 1) << 7;

    const float* W;
    const float* bias;
    float* out;
    if (sel == 0)      { W = Wq; bias = bq; out = g_q; }
    else if (sel == 1) { W = Wk; bias = bk; out = g_k; }
    else               { W = Wv; bias = bv; out = g_v; }

    gemm_tf32(g_xn + (size_t)bl * HW * CC,
              W + (size_t)t * CC * II,
              bias + (size_t)t * II,
              out + (size_t)bl * HW * II,
              blockIdx.x << 7, ncol0);
}

// =====================================================================
// Kernel 3: fused HGT attention (unchanged from passing R2 kernel).
// Block = 256 threads (8 warps), each warp owns one (b, m, hw).
// grid = B*M*(HW/8) = 4096
// =====================================================================
__global__ __launch_bounds__(256) void k_attn(const int*   __restrict__ mask,
                                              const float* __restrict__ pe,
                                              const float* __restrict__ rel_att,
                                              const float* __restrict__ rel_msg)
{
    __shared__ float Wa_s[4][33 * 32];   // att weights, layout [r][q*33 + p]
    __shared__ float Wm_s[4][33 * 32];   // msg weights, layout [r][p*33 + c]
    __shared__ float ks_s[8][LL][32];
    __shared__ float vs_s[8][LL][32];
    __shared__ int   ts_s[LL];

    int tid  = threadIdx.x;
    int lane = tid & 31;
    int w    = tid >> 5;
    int bidx = blockIdx.x;
    int hw   = ((bidx & 127) << 3) + w;
    int m    = (bidx >> 7) & 7;
    int b    = bidx >> 10;

    if (tid < LL) ts_s[tid] = (int)pe[(size_t)(b * LL + tid) * 3072 + 2];

    // stage relation matrices for this head (4 e-values, both att & msg)
    for (int idx = tid; idx < 4096; idx += 256) {
        int r   = idx >> 10;
        int rem = idx & 1023;
        int p   = rem >> 5;
        int qq  = rem & 31;
        size_t goff = (size_t)(r * MM + m) * 1024 + rem;
        Wa_s[r][qq * 33 + p] = rel_att[goff];   // transposed: [q][p]
        Wm_s[r][p * 33 + qq] = rel_msg[goff];   // direct:     [p][c]
    }

    // stage q (regs) and k/v (smem)
    float qreg[LL];
    int base_off = (m << 5) + lane;
    #pragma unroll
    for (int j = 0; j < LL; ++j) {
        size_t tok = (size_t)((b * LL + j) << 10) + hw;
        qreg[j]        = g_q[tok * II + base_off];
        ks_s[w][j][lane] = g_k[tok * II + base_off];
        vs_s[w][j][lane] = g_v[tok * II + base_off];
    }
    __syncthreads();

    // relation transforms (only T=2 query-type variants needed)
    float kp[LL][2], vp[LL][2];
    #pragma unroll
    for (int j = 0; j < LL; ++j) {
        int tj = ts_s[j];
        const float* WA0 = Wa_s[tj];
        const float* WA1 = Wa_s[2 + tj];
        const float* WM0 = Wm_s[tj];
        const float* WM1 = Wm_s[2 + tj];
        float a0 = 0.f, a1 = 0.f, s0 = 0.f, s1 = 0.f;
        #pragma unroll
        for (int qq = 0; qq < 32; ++qq) {
            float kv = ks_s[w][j][qq];
            float vv = vs_s[w][j][qq];
            int off = qq * 33 + lane;
            a0 = fmaf(WA0[off], kv, a0);
            a1 = fmaf(WA1[off], kv, a1);
            s0 = fmaf(WM0[off], vv, s0);
            s1 = fmaf(WM1[off], vv, s1);
        }
        kp[j][0] = a0; kp[j][1] = a1;
        vp[j][0] = s0; vp[j][1] = s1;
    }

    // att[i][j] = scale * q_i . k'_{j, t_i}
    float att[LL][LL];
    #pragma unroll
    for (int i = 0; i < LL; ++i) {
        int ti = ts_s[i];
        #pragma unroll
        for (int j = 0; j < LL; ++j) {
            float kpv  = ti ? kp[j][1] : kp[j][0];
            float part = qreg[i] * kpv;
            part += __shfl_xor_sync(0xffffffffu, part, 16);
            part += __shfl_xor_sync(0xffffffffu, part, 8);
            part += __shfl_xor_sync(0xffffffffu, part, 4);
            part += __shfl_xor_sync(0xffffffffu, part, 2);
            part += __shfl_xor_sync(0xffffffffu, part, 1);
            att[i][j] = part * 0.17677669529663687f;   // D^-0.5
        }
    }

    // mask + softmax + weighted message accumulation + store
    const int* mrow = mask + ((size_t)(b << 10) + hw) * 25;
    #pragma unroll
    for (int i = 0; i < LL; ++i) {
        float mx = -1e30f;
        #pragma unroll
        for (int j = 0; j < LL; ++j) {
            if (mrow[i * 5 + j] == 0) att[i][j] = -1e9f;
            mx = fmaxf(mx, att[i][j]);
        }
        float s = 0.f;
        #pragma unroll
        for (int j = 0; j < LL; ++j) {
            float e = __expf(att[i][j] - mx);
            att[i][j] = e;
            s += e;
        }
        float inv = 1.0f / s;
        int ti = ts_s[i];
        float o = 0.f;
        #pragma unroll
        for (int j = 0; j < LL; ++j) {
            float vpv = ti ? vp[j][1] : vp[j][0];
            o = fmaf(att[i][j], vpv, o);
        }
        size_t tok = (size_t)((b * LL + i) << 10) + hw;
        g_ao[tok * II + base_off] = o * inv;
    }
}

// =====================================================================
// Kernel 4: output projection + bias -> final output. grid = (8,2,20)
// =====================================================================
__global__ __launch_bounds__(256, 1) void k_gemm_ao(const float* __restrict__ pe,
                                                    const float* __restrict__ Wa,
                                                    const float* __restrict__ ba,
                                                    float* __restrict__ out)
{
    int bl = blockIdx.z;
    int t  = (int)pe[(size_t)bl * 3072 + 2];
    gemm_tf32(g_ao + (size_t)bl * HW * II,
              Wa + (size_t)t * II * CC,
              ba + (size_t)t * CC,
              out + (size_t)bl * HW * CC,
              blockIdx.x << 7, (blockIdx.y & 1) << 7);
}

// =====================================================================
extern "C" void kernel_launch(void* const* d_in, const int* in_sizes, int n_in,
                              void* d_out, int out_size)
{
    const float* x    = (const float*)d_in[0];
    const int*   mask = (const int*)  d_in[1];
    const float* pe   = (const float*)d_in[2];
    const float* lnw  = (const float*)d_in[3];
    const float* lnb  = (const float*)d_in[4];
    const float* Wq   = (const float*)d_in[5];
    const float* bq   = (const float*)d_in[6];
    const float* Wk   = (const float*)d_in[7];
    const float* bk   = (const float*)d_in[8];
    const float* Wv   = (const float*)d_in[9];
    const float* bv   = (const float*)d_in[10];
    const float* Wa   = (const float*)d_in[11];
    const float* ba   = (const float*)d_in[12];
    const float* ra   = (const float*)d_in[13];
    const float* rm   = (const float*)d_in[14];
    float* out = (float*)d_out;

    k_ln<<<2560, 256>>>(x, lnw, lnb);

    dim3 g1(8, 6, 20);
    k_gemm_qkv<<<g1, 256>>>(pe, Wq, bq, Wk, bk, Wv, bv);

    k_attn<<<4096, 256>>>(mask, pe, ra, rm);

    dim3 g2(8, 2, 20);
    k_gemm_ao<<<g2, 256>>>(pe, Wa, ba, out);
}